// round 12
// baseline (speedup 1.0000x reference)
#include <cuda_runtime.h>
#include <cuda_fp16.h>
#include <cstdint>

#define KC   512
#define DD   64
#define TPB  256
#define BN   128
#define LDA  72
#define ROWB 144

// main smem (R5 layout, M-term buffer removed)
#define OFF_AH   0                     // 128 x 144B (h of x)
#define OFF_AM   18432                 // 128 x 144B (m of x)
#define OFF_BH   36864                 // 128 x 144B (H of codes, single buffer)
#define OFF_HWW  55296                 // 128 f32
#define OFF_NX   55808                 // 128 f32 ||x||^2
#define OFF_NR   56320                 // 128 f32 ||rho||^2
#define OFF_SBV  56832                 // 128x2 f32 best
#define OFF_SB2  57856                 // 128x2 f32 second
#define OFF_SBI  58880                 // 128x2 i32
#define OFF_KF   59904                 // 128 u32 (k | flag<<31)
#define OFF_SRED 60416                 // 8 dbl
#define SMEM_TOTAL 60480

// rescore smem
#define RS_SW    0                     // 64 x 520 f32 codebook [d][k]
#define RS_SX    133120                // 8 x 64 f32
#define RS_SRED  135168
#define RS_TOTAL 135232

__device__ __align__(16) __half g_bh[KC * LDA];    // fp16 H of codebook [k][d]
__device__ __align__(16) float  g_embT[KC * DD];   // fp32 codebook [k][d]
__device__ __align__(16) float  g_hww[KC];         // 0.5*||w||^2
__device__ unsigned g_Rmax;                        // max_k ||w_k - fp32(H_k)|| (bits)
__device__ unsigned g_Wmax;                        // max_k ||w_k|| (bits)
__device__ int      g_wl[65536];
__device__ unsigned g_wl_count;
__device__ double   g_loss_sum;
__device__ unsigned g_rctr;

#define LDSM4(r0, r1, r2, r3, addr) \
    asm volatile("ldmatrix.sync.aligned.m8n8.x4.shared.b16 {%0,%1,%2,%3}, [%4];" \
                 : "=r"(r0), "=r"(r1), "=r"(r2), "=r"(r3) : "r"(addr))

#define MMA(d, a, b) \
    asm volatile("mma.sync.aligned.m16n8k16.row.col.f32.f16.f16.f32 " \
                 "{%0,%1,%2,%3}, {%4,%5,%6,%7}, {%8,%9}, {%0,%1,%2,%3};" \
                 : "+f"((d)[0]), "+f"((d)[1]), "+f"((d)[2]), "+f"((d)[3]) \
                 : "r"((a)[0]), "r"((a)[1]), "r"((a)[2]), "r"((a)[3]), \
                   "r"((b)[0]), "r"((b)[1]))

#define CPA16(dst, src) \
    asm volatile("cp.async.cg.shared.global [%0], [%1], 16;" :: "r"(dst), "l"(src))

// ---- pre: emb -> g_bh (fp16 H [k][d]), g_embT (fp32), g_hww, Rmax, Wmax ----
__global__ void __launch_bounds__(128)
vq_pre_kernel(const float* __restrict__ emb)
{
    __shared__ float sp[4][32], sr[4][32];
    const int t = threadIdx.x;
    const int c = blockIdx.x * 32 + (t & 31);
    const int dseg = (t >> 5) * 16;

    float e[16];
    uint32_t hw[8];
    float s = 0.f, srr = 0.f;
    #pragma unroll
    for (int j = 0; j < 8; j++) {
        float e0 = __ldg(emb + (size_t)(dseg + 2 * j) * KC + c);
        float e1 = __ldg(emb + (size_t)(dseg + 2 * j + 1) * KC + c);
        e[2 * j] = e0; e[2 * j + 1] = e1;
        s = fmaf(e1, e1, fmaf(e0, e0, s));
        __half h0 = __float2half_rn(e0), h1 = __float2half_rn(e1);
        float r0 = e0 - __half2float(h0), r1 = e1 - __half2float(h1);
        srr = fmaf(r1, r1, fmaf(r0, r0, srr));
        hw[j] = (uint32_t)__half_as_ushort(h0) | ((uint32_t)__half_as_ushort(h1) << 16);
    }
    *(uint4*)(g_bh + c * LDA + dseg)     = make_uint4(hw[0], hw[1], hw[2], hw[3]);
    *(uint4*)(g_bh + c * LDA + dseg + 8) = make_uint4(hw[4], hw[5], hw[6], hw[7]);
    float* et = g_embT + (size_t)c * DD + dseg;
    #pragma unroll
    for (int j = 0; j < 4; j++)
        *(float4*)(et + 4 * j) = make_float4(e[4 * j], e[4 * j + 1], e[4 * j + 2], e[4 * j + 3]);
    sp[t >> 5][t & 31] = s;
    sr[t >> 5][t & 31] = srr;
    __syncthreads();
    if (t < 32) {
        float tot  = sp[0][t] + sp[1][t] + sp[2][t] + sp[3][t];
        float rtot = sr[0][t] + sr[1][t] + sr[2][t] + sr[3][t];
        g_hww[blockIdx.x * 32 + t] = 0.5f * tot;
        atomicMax(&g_Wmax, __float_as_uint(sqrtf(tot)));
        atomicMax(&g_Rmax, __float_as_uint(sqrtf(rtot)));
    }
}

__global__ void __launch_bounds__(TPB, 2)
vq_main_kernel(const float* __restrict__ x, float* __restrict__ out_q,
               float* __restrict__ out_idx, int n_rows)
{
    extern __shared__ char smem[];
    const uint32_t sb = (uint32_t)__cvta_generic_to_shared(smem);
    const int t = threadIdx.x, lane = t & 31, w = t >> 5;
    const int wm = w >> 1, wn = w & 1;       // 4 m-warps x 2 n-warps
    const int rowbase = blockIdx.x * BN;

    // ---- A split: x -> h + m fp16; exact residual rho tracked per row ----
    {
        const int row = t >> 1, hseg = (t & 1) * 32;
        const bool valid = (rowbase + row) < n_rows;
        const float4* xr = (const float4*)(x + (size_t)(rowbase + row) * DD + hseg);
        __half* ah = (__half*)(smem + OFF_AH) + row * LDA + hseg;
        __half* am = (__half*)(smem + OFF_AM) + row * LDA + hseg;
        float nx = 0.f, nr = 0.f;
        #pragma unroll
        for (int j = 0; j < 8; j++) {
            float4 f = valid ? xr[j] : make_float4(0.f, 0.f, 0.f, 0.f);
            float e[4] = {f.x, f.y, f.z, f.w};
            __half h[4], m[4];
            #pragma unroll
            for (int p = 0; p < 4; p++) {
                nx = fmaf(e[p], e[p], nx);
                h[p] = __float2half_rn(e[p]);
                float r1 = e[p] - __half2float(h[p]);
                m[p] = __float2half_rn(r1);
                float rho = r1 - __half2float(m[p]);
                nr = fmaf(rho, rho, nr);
            }
            *(__half2*)(ah + 4 * j)     = __halves2half2(h[0], h[1]);
            *(__half2*)(ah + 4 * j + 2) = __halves2half2(h[2], h[3]);
            *(__half2*)(am + 4 * j)     = __halves2half2(m[0], m[1]);
            *(__half2*)(am + 4 * j + 2) = __halves2half2(m[2], m[3]);
        }
        nx += __shfl_xor_sync(0xffffffffu, nx, 1);
        nr += __shfl_xor_sync(0xffffffffu, nr, 1);
        if ((t & 1) == 0) {
            ((float*)(smem + OFF_NX))[row] = nx;
            ((float*)(smem + OFF_NR))[row] = nr;
        }
    }

    float b1v[4], b2v[4];
    int   b1i[4];
    #pragma unroll
    for (int s = 0; s < 4; s++) { b1v[s] = -3.402823466e38f; b2v[s] = -3.402823466e38f; b1i[s] = 0; }

    const uint32_t a_off = (uint32_t)((wm * 32 + (lane & 15)) * ROWB + (((lane >> 4) << 3) << 1));
    const uint32_t b_off = (uint32_t)(((lane & 7) + ((lane >> 4) << 3) + wn * 64) * ROWB
                                      + ((((lane >> 3) & 1) << 3) << 1));

    #pragma unroll 1
    for (int q = 0; q < 4; q++) {
        const int qbase = q * 128;
        __syncthreads();   // prior quarter's ldmatrix done; BH free (A ready at q=0)

        // ---- copy pre-split H quarter + hww (L2-hot, contiguous) ----
        {
            const char* srcH = (const char*)g_bh + (size_t)qbase * ROWB;
            #pragma unroll
            for (int i = t; i < 1152; i += TPB)
                CPA16(sb + OFF_BH + i * 16, srcH + i * 16);
            if (t < 32) CPA16(sb + OFF_HWW + t * 16, (const char*)g_hww + qbase * 4 + t * 16);
            asm volatile("cp.async.commit_group;");
            asm volatile("cp.async.wait_group 0;" ::: "memory");
        }
        __syncthreads();

        // ---- 2-term MMA: acc = (h+m).H - 0.5||w||^2 ----
        float acc[2][8][4];
        {
            const float* hww = (const float*)(smem + OFF_HWW);
            #pragma unroll
            for (int nt = 0; nt < 8; nt++) {
                float2 hv = *(const float2*)(hww + wn * 64 + nt * 8 + 2 * (lane & 3));
                #pragma unroll
                for (int mt = 0; mt < 2; mt++) {
                    acc[mt][nt][0] = -hv.x; acc[mt][nt][1] = -hv.y;
                    acc[mt][nt][2] = -hv.x; acc[mt][nt][3] = -hv.y;
                }
            }
        }
        #pragma unroll
        for (int kc = 0; kc < 4; kc++) {
            const uint32_t ka = (uint32_t)(kc * 32);
            uint32_t ah[2][4], am[2][4], bb[8][2];
            LDSM4(ah[0][0], ah[0][1], ah[0][2], ah[0][3], sb + OFF_AH + a_off + ka);
            LDSM4(ah[1][0], ah[1][1], ah[1][2], ah[1][3], sb + OFF_AH + a_off + ka + 16 * ROWB);
            LDSM4(am[0][0], am[0][1], am[0][2], am[0][3], sb + OFF_AM + a_off + ka);
            LDSM4(am[1][0], am[1][1], am[1][2], am[1][3], sb + OFF_AM + a_off + ka + 16 * ROWB);
            #pragma unroll
            for (int ng = 0; ng < 4; ng++)
                LDSM4(bb[2 * ng][0], bb[2 * ng][1], bb[2 * ng + 1][0], bb[2 * ng + 1][1],
                      sb + OFF_BH + b_off + ka + ng * 16 * ROWB);
            #pragma unroll
            for (int mt = 0; mt < 2; mt++)
                #pragma unroll
                for (int nt = 0; nt < 8; nt++) {
                    MMA(acc[mt][nt], ah[mt], bb[nt]);   // h.H
                    MMA(acc[mt][nt], am[mt], bb[nt]);   // m.H
                }
        }

        // ---- scan with best + second-best (strict >, ascending) ----
        #pragma unroll
        for (int mt = 0; mt < 2; mt++)
            #pragma unroll
            for (int nt = 0; nt < 8; nt++) {
                const int c0 = qbase + wn * 64 + nt * 8 + 2 * (lane & 3);
                #pragma unroll
                for (int rh = 0; rh < 2; rh++) {
                    const int s = mt * 2 + rh;
                    #pragma unroll
                    for (int hv = 0; hv < 2; hv++) {
                        float v = acc[mt][nt][rh * 2 + hv];
                        if (v > b1v[s]) { b2v[s] = b1v[s]; b1v[s] = v; b1i[s] = c0 + hv; }
                        else if (v > b2v[s]) b2v[s] = v;
                    }
                }
            }
    }
    __syncthreads();

    // ---- width-4 reduce (best+second) ----
    #pragma unroll
    for (int s = 0; s < 4; s++) {
        float v1 = b1v[s], v2 = b2v[s]; int i1 = b1i[s];
        #pragma unroll
        for (int off = 1; off <= 2; off <<= 1) {
            float ov = __shfl_xor_sync(0xffffffffu, v1, off);
            float o2 = __shfl_xor_sync(0xffffffffu, v2, off);
            int   oi = __shfl_xor_sync(0xffffffffu, i1, off);
            bool take = (ov > v1) || (ov == v1 && oi < i1);
            float vloser = take ? v1 : ov;
            v2 = fmaxf(fmaxf(v2, o2), vloser);
            if (take) { v1 = ov; i1 = oi; }
        }
        if ((lane & 3) == 0) {
            int row = wm * 32 + (s >> 1) * 16 + (s & 1) * 8 + (lane >> 2);
            ((float*)(smem + OFF_SBV))[row * 2 + wn] = v1;
            ((float*)(smem + OFF_SB2))[row * 2 + wn] = v2;
            ((int*)(smem + OFF_SBI))[row * 2 + wn] = i1;
        }
    }
    __syncthreads();

    // ---- merge n-warps, sound margin test, worklist ----
    if (t < 128) {
        float v1a = ((float*)(smem + OFF_SBV))[t * 2 + 0];
        float v1b = ((float*)(smem + OFF_SBV))[t * 2 + 1];
        float v2a = ((float*)(smem + OFF_SB2))[t * 2 + 0];
        float v2b = ((float*)(smem + OFF_SB2))[t * 2 + 1];
        int   ia  = ((int*)(smem + OFF_SBI))[t * 2 + 0];
        int   ib  = ((int*)(smem + OFF_SBI))[t * 2 + 1];
        bool take = (v1b > v1a) || (v1b == v1a && ib < ia);
        float bb1 = take ? v1b : v1a;
        int   k   = take ? ib : ia;
        float bb2 = fmaxf(fmaxf(v2a, v2b), fminf(v1a, v1b));
        // per-score error <= ||x||*Rmax + ||rho||*Wmax + fp32-accum slack
        float eps = sqrtf(((float*)(smem + OFF_NX))[t]) * __uint_as_float(g_Rmax)
                  + sqrtf(((float*)(smem + OFF_NR))[t]) * __uint_as_float(g_Wmax)
                  + 1e-4f;
        bool valid = (rowbase + t) < n_rows;
        bool flag = valid && (bb1 - bb2 <= 2.0f * eps);
        ((unsigned*)(smem + OFF_KF))[t] = (unsigned)k | (flag ? 0x80000000u : 0u);
        if (valid) out_idx[rowbase + t] = (float)k;
        if (flag) { unsigned pos = atomicAdd(&g_wl_count, 1u); g_wl[pos] = rowbase + t; }
    }
    __syncthreads();

    // ---- epilogue: q from g_embT (exact fp32), loss for non-flagged ----
    double lsum = 0.0;
    {
        const int row = t >> 1, hseg = (t & 1) * 32;
        const int grow = rowbase + row;
        if (grow < n_rows) {
            unsigned kf = ((unsigned*)(smem + OFF_KF))[row];
            const int k = (int)(kf & 0x7fffffffu);
            const bool flag = (kf & 0x80000000u) != 0u;
            const float4* wp = (const float4*)(g_embT + (size_t)k * DD + hseg);
            const float4* xr = (const float4*)(x + (size_t)grow * DD + hseg);
            float4* qo = (float4*)(out_q + (size_t)grow * DD + hseg);
            #pragma unroll
            for (int j = 0; j < 8; j++) {
                float4 qv = wp[j];
                qo[j] = qv;
                if (!flag) {
                    float4 xv = xr[j];
                    float e0 = qv.x - xv.x, e1 = qv.y - xv.y;
                    float e2 = qv.z - xv.z, e3 = qv.w - xv.w;
                    lsum += (double)(e0 * e0 + e1 * e1 + e2 * e2 + e3 * e3);
                }
            }
        }
    }

    #pragma unroll
    for (int off = 16; off; off >>= 1) lsum += __shfl_down_sync(0xffffffffu, lsum, off);
    double* sred = (double*)(smem + OFF_SRED);
    if (lane == 0) sred[w] = lsum;
    __syncthreads();
    if (t == 0) {
        double v = 0.0;
        #pragma unroll
        for (int i = 0; i < 8; i++) v += sred[i];
        atomicAdd(&g_loss_sum, v);
    }
}

// ---- rescore flagged rows exactly in fp32; finalize loss; reset state ----
__global__ void __launch_bounds__(256)
vq_rescore_kernel(const float* __restrict__ x, const float* __restrict__ emb,
                  float* __restrict__ out_q, float* __restrict__ out_idx,
                  float* __restrict__ out_loss, double inv_count)
{
    extern __shared__ char smem[];
    float* sw = (float*)(smem + RS_SW);              // [64][520]
    float* sx = (float*)(smem + RS_SX);              // [8][64]
    double* sred = (double*)(smem + RS_SRED);
    const int t = threadIdx.x, lane = t & 31, w = t >> 5;
    const unsigned count = g_wl_count;
    const int gw = blockIdx.x * 8 + w;
    const int stride = gridDim.x * 8;

    double lsum = 0.0;
    if ((unsigned)(blockIdx.x * 8) < count) {
        for (int idx = t; idx < 64 * 128; idx += 256) {
            int d = idx >> 7, p = idx & 127;
            float4 v = ((const float4*)emb)[idx];
            *(float4*)(sw + d * 520 + 4 * p) = v;
        }
        __syncthreads();

        for (unsigned i = gw; i < count; i += stride) {
            const int row = g_wl[i];
            float x0 = x[(size_t)row * DD + lane];
            float x1 = x[(size_t)row * DD + 32 + lane];
            sx[w * 64 + lane] = x0;
            sx[w * 64 + 32 + lane] = x1;
            __syncwarp();

            float acc[16];
            #pragma unroll
            for (int j = 0; j < 16; j++) acc[j] = -g_hww[lane + 32 * j];
            #pragma unroll 4
            for (int d = 0; d < DD; d++) {
                float xd = sx[w * 64 + d];
                const float* wr = sw + d * 520 + lane;
                #pragma unroll
                for (int j = 0; j < 16; j++)
                    acc[j] = fmaf(xd, wr[32 * j], acc[j]);
            }
            float bv = -3.402823466e38f; int bk = 0;
            #pragma unroll
            for (int j = 0; j < 16; j++)
                if (acc[j] > bv) { bv = acc[j]; bk = lane + 32 * j; }
            #pragma unroll
            for (int off = 16; off; off >>= 1) {
                float ov = __shfl_xor_sync(0xffffffffu, bv, off);
                int   oi = __shfl_xor_sync(0xffffffffu, bk, off);
                if (ov > bv || (ov == bv && oi < bk)) { bv = ov; bk = oi; }
            }
            float q0 = sw[lane * 520 + bk];
            float q1 = sw[(lane + 32) * 520 + bk];
            out_q[(size_t)row * DD + lane] = q0;
            out_q[(size_t)row * DD + 32 + lane] = q1;
            float e0 = q0 - x0, e1 = q1 - x1;
            float err = e0 * e0 + e1 * e1;
            #pragma unroll
            for (int off = 16; off; off >>= 1) err += __shfl_down_sync(0xffffffffu, err, off);
            if (lane == 0) { lsum += (double)err; out_idx[row] = (float)bk; }
        }
    }

    if (lane == 0) sred[w] = lsum;
    __syncthreads();
    if (t == 0) {
        double v = 0.0;
        #pragma unroll
        for (int i = 0; i < 8; i++) v += sred[i];
        atomicAdd(&g_loss_sum, v);
        __threadfence();
        unsigned prev = atomicAdd(&g_rctr, 1u);
        if (prev == gridDim.x - 1) {
            __threadfence();
            double total = atomicAdd(&g_loss_sum, 0.0);
            *out_loss = (float)(1.25 * total * inv_count);
            g_loss_sum = 0.0;
            g_wl_count = 0u;
            g_rctr = 0u;
        }
    }
}

extern "C" void kernel_launch(void* const* d_in, const int* in_sizes, int n_in,
                              void* d_out, int out_size)
{
    const float* x   = (const float*)d_in[0];   // [N, 64]
    const float* emb = (const float*)d_in[1];   // [64, 512]

    const int n_rows = in_sizes[0] / DD;
    float* out      = (float*)d_out;
    float* out_q    = out;
    float* out_idx  = out + (size_t)n_rows * DD;
    float* out_loss = out_idx + n_rows;

    cudaFuncSetAttribute(vq_main_kernel,
                         cudaFuncAttributeMaxDynamicSharedMemorySize, SMEM_TOTAL);
    cudaFuncSetAttribute(vq_rescore_kernel,
                         cudaFuncAttributeMaxDynamicSharedMemorySize, RS_TOTAL);

    int grid = (n_rows + BN - 1) / BN;   // 512

    vq_pre_kernel<<<16, 128>>>(emb);
    vq_main_kernel<<<grid, TPB, SMEM_TOTAL>>>(x, out_q, out_idx, n_rows);
    vq_rescore_kernel<<<64, 256, RS_TOTAL>>>(x, emb, out_q, out_idx, out_loss,
                                             1.0 / ((double)n_rows * (double)DD));
}

// round 13
// speedup vs baseline: 1.1635x; 1.1635x over previous
#include <cuda_runtime.h>
#include <cuda_fp16.h>
#include <cstdint>

#define KC   512
#define DD   64
#define TPB  512
#define BN   256
#define LDA  72
#define ROWB 144

// smem: A (h,m) for 256 rows + FULL pre-split codebook (H,M) + hww
#define OFF_AH   0                     // 256 x 144B
#define OFF_AM   36864                 // 256 x 144B
#define OFF_BH   73728                 // 512 x 144B
#define OFF_BM   147456                // 512 x 144B
#define OFF_HWW  221184                // 512 f32
#define SMEM_TOTAL 223232              // 218 KB -> 1 CTA/SM
// post-loop overlay (inside OFF_BH region, after final syncthreads)
#define OFF_SBV  (OFF_BH)              // 256x2 f32
#define OFF_SBI  (OFF_BH + 2048)       // 256x2 i32
#define OFF_KIDX (OFF_BH + 4096)       // 256 i32
#define OFF_SRED (OFF_BH + 5120)       // 16 dbl

__device__ __align__(16) __half g_bh[KC * LDA];    // fp16 h of codebook [k][d]
__device__ __align__(16) __half g_bm[KC * LDA];    // fp16 m of codebook
__device__ __align__(16) float  g_embT[KC * DD];   // fp32 codebook [k][d]
__device__ __align__(16) float  g_hww[KC];         // 0.5*||w||^2
__device__ double   g_loss_sum;
__device__ unsigned g_ctr;

#define LDSM4(r0, r1, r2, r3, addr) \
    asm volatile("ldmatrix.sync.aligned.m8n8.x4.shared.b16 {%0,%1,%2,%3}, [%4];" \
                 : "=r"(r0), "=r"(r1), "=r"(r2), "=r"(r3) : "r"(addr))

#define MMA(d, a, b) \
    asm volatile("mma.sync.aligned.m16n8k16.row.col.f32.f16.f16.f32 " \
                 "{%0,%1,%2,%3}, {%4,%5,%6,%7}, {%8,%9}, {%0,%1,%2,%3};" \
                 : "+f"((d)[0]), "+f"((d)[1]), "+f"((d)[2]), "+f"((d)[3]) \
                 : "r"((a)[0]), "r"((a)[1]), "r"((a)[2]), "r"((a)[3]), \
                   "r"((b)[0]), "r"((b)[1]))

#define CPA16(dst, src) \
    asm volatile("cp.async.cg.shared.global [%0], [%1], 16;" :: "r"(dst), "l"(src))

// ---- pre: emb [64][512] -> g_bh/g_bm (fp16 h/m [k][d]), g_embT (fp32), g_hww ----
__global__ void __launch_bounds__(128)
vq_pre_kernel(const float* __restrict__ emb)
{
    __shared__ float sp[4][32];
    const int t = threadIdx.x;
    const int c = blockIdx.x * 32 + (t & 31);
    const int dseg = (t >> 5) * 16;

    float e[16];
    uint32_t hw[8], mw[8];
    float s = 0.f;
    #pragma unroll
    for (int j = 0; j < 8; j++) {
        float e0 = __ldg(emb + (size_t)(dseg + 2 * j) * KC + c);
        float e1 = __ldg(emb + (size_t)(dseg + 2 * j + 1) * KC + c);
        e[2 * j] = e0; e[2 * j + 1] = e1;
        s = fmaf(e1, e1, fmaf(e0, e0, s));
        __half h0 = __float2half_rn(e0), h1 = __float2half_rn(e1);
        __half m0 = __float2half_rn(e0 - __half2float(h0));
        __half m1 = __float2half_rn(e1 - __half2float(h1));
        hw[j] = (uint32_t)__half_as_ushort(h0) | ((uint32_t)__half_as_ushort(h1) << 16);
        mw[j] = (uint32_t)__half_as_ushort(m0) | ((uint32_t)__half_as_ushort(m1) << 16);
    }
    *(uint4*)(g_bh + c * LDA + dseg)     = make_uint4(hw[0], hw[1], hw[2], hw[3]);
    *(uint4*)(g_bh + c * LDA + dseg + 8) = make_uint4(hw[4], hw[5], hw[6], hw[7]);
    *(uint4*)(g_bm + c * LDA + dseg)     = make_uint4(mw[0], mw[1], mw[2], mw[3]);
    *(uint4*)(g_bm + c * LDA + dseg + 8) = make_uint4(mw[4], mw[5], mw[6], mw[7]);
    float* et = g_embT + (size_t)c * DD + dseg;
    #pragma unroll
    for (int j = 0; j < 4; j++)
        *(float4*)(et + 4 * j) = make_float4(e[4 * j], e[4 * j + 1], e[4 * j + 2], e[4 * j + 3]);
    sp[t >> 5][t & 31] = s;
    __syncthreads();
    if (t < 32)
        g_hww[blockIdx.x * 32 + t] = 0.5f * (sp[0][t] + sp[1][t] + sp[2][t] + sp[3][t]);
}

__global__ void __launch_bounds__(TPB, 1)
vq_main_kernel(const float* __restrict__ x, float* __restrict__ out_q,
               float* __restrict__ out_idx, float* __restrict__ out_loss,
               int n_rows, double inv_count)
{
    extern __shared__ char smem[];
    const uint32_t sb = (uint32_t)__cvta_generic_to_shared(smem);
    const int t = threadIdx.x, lane = t & 31, w = t >> 5;
    const int wm = w >> 1, wn = w & 1;       // 8 m-warps x 2 n-warps
    const int rowbase = blockIdx.x * BN;

    // ---- prologue: issue ALL 4 quarter-copies of the codebook (4 commit groups) ----
    #pragma unroll
    for (int q = 0; q < 4; q++) {
        const char* srcH = (const char*)g_bh + (size_t)q * 128 * ROWB;
        const char* srcM = (const char*)g_bm + (size_t)q * 128 * ROWB;
        const uint32_t dH = sb + OFF_BH + q * 128 * ROWB;
        const uint32_t dM = sb + OFF_BM + q * 128 * ROWB;
        for (int i = t; i < 1152; i += TPB) {   // 128*144B/16
            CPA16(dH + i * 16, srcH + i * 16);
            CPA16(dM + i * 16, srcM + i * 16);
        }
        if (t < 32) CPA16(sb + OFF_HWW + q * 512 + t * 16,
                          (const char*)g_hww + q * 512 + t * 16);
        asm volatile("cp.async.commit_group;");
    }

    // ---- A split: x -> h (AH) + m (AM) fp16 tiles (overlaps codebook copies) ----
    {
        const int row = t >> 1, hseg = (t & 1) * 32;
        const bool valid = (rowbase + row) < n_rows;
        const float4* xr = (const float4*)(x + (size_t)(rowbase + row) * DD + hseg);
        __half* ah = (__half*)(smem + OFF_AH) + row * LDA + hseg;
        __half* am = (__half*)(smem + OFF_AM) + row * LDA + hseg;
        #pragma unroll
        for (int j = 0; j < 8; j++) {
            float4 f = valid ? xr[j] : make_float4(0.f, 0.f, 0.f, 0.f);
            float e[4] = {f.x, f.y, f.z, f.w};
            __half h[4], m[4];
            #pragma unroll
            for (int p = 0; p < 4; p++) {
                h[p] = __float2half_rn(e[p]);
                m[p] = __float2half_rn(e[p] - __half2float(h[p]));
            }
            *(__half2*)(ah + 4 * j)     = __halves2half2(h[0], h[1]);
            *(__half2*)(ah + 4 * j + 2) = __halves2half2(h[2], h[3]);
            *(__half2*)(am + 4 * j)     = __halves2half2(m[0], m[1]);
            *(__half2*)(am + 4 * j + 2) = __halves2half2(m[2], m[3]);
        }
    }
    __syncthreads();   // A tiles visible

    float best[4];
    int   bk[4];
    #pragma unroll
    for (int s = 0; s < 4; s++) { best[s] = -3.402823466e38f; bk[s] = 0; }

    const uint32_t a_off = (uint32_t)((wm * 32 + (lane & 15)) * ROWB + (((lane >> 4) << 3) << 1));
    const uint32_t b_off = (uint32_t)(((lane & 7) + ((lane >> 4) << 3) + wn * 64) * ROWB
                                      + ((((lane >> 3) & 1) << 3) << 1));

    #pragma unroll 1
    for (int q = 0; q < 4; q++) {
        // quarter q's copies landed long ago; wait is ~free, barrier for x-thread visibility
        if      (q == 0) asm volatile("cp.async.wait_group 3;" ::: "memory");
        else if (q == 1) asm volatile("cp.async.wait_group 2;" ::: "memory");
        else if (q == 2) asm volatile("cp.async.wait_group 1;" ::: "memory");
        else             asm volatile("cp.async.wait_group 0;" ::: "memory");
        __syncthreads();

        const uint32_t bh_base = sb + OFF_BH + q * 128 * ROWB;
        const uint32_t bm_base = sb + OFF_BM + q * 128 * ROWB;

        // ---- 3-term MMA: acc = hH + mH + hM - 0.5||w||^2 ----
        float acc[2][8][4];
        {
            const float* hww = (const float*)(smem + OFF_HWW + q * 512);
            #pragma unroll
            for (int nt = 0; nt < 8; nt++) {
                float2 hv = *(const float2*)(hww + wn * 64 + nt * 8 + 2 * (lane & 3));
                #pragma unroll
                for (int mt = 0; mt < 2; mt++) {
                    acc[mt][nt][0] = -hv.x; acc[mt][nt][1] = -hv.y;
                    acc[mt][nt][2] = -hv.x; acc[mt][nt][3] = -hv.y;
                }
            }
        }
        #pragma unroll
        for (int kc = 0; kc < 4; kc++) {
            const uint32_t ka = (uint32_t)(kc * 32);
            uint32_t ah[2][4], am[2][4], bb[8][2];
            LDSM4(ah[0][0], ah[0][1], ah[0][2], ah[0][3], sb + OFF_AH + a_off + ka);
            LDSM4(ah[1][0], ah[1][1], ah[1][2], ah[1][3], sb + OFF_AH + a_off + ka + 16 * ROWB);
            LDSM4(am[0][0], am[0][1], am[0][2], am[0][3], sb + OFF_AM + a_off + ka);
            LDSM4(am[1][0], am[1][1], am[1][2], am[1][3], sb + OFF_AM + a_off + ka + 16 * ROWB);
            #pragma unroll
            for (int ng = 0; ng < 4; ng++)
                LDSM4(bb[2 * ng][0], bb[2 * ng][1], bb[2 * ng + 1][0], bb[2 * ng + 1][1],
                      bh_base + b_off + ka + ng * 16 * ROWB);
            #pragma unroll
            for (int mt = 0; mt < 2; mt++)
                #pragma unroll
                for (int nt = 0; nt < 8; nt++) {
                    MMA(acc[mt][nt], ah[mt], bb[nt]);   // h.H
                    MMA(acc[mt][nt], am[mt], bb[nt]);   // m.H
                }
            #pragma unroll
            for (int ng = 0; ng < 4; ng++)
                LDSM4(bb[2 * ng][0], bb[2 * ng][1], bb[2 * ng + 1][0], bb[2 * ng + 1][1],
                      bm_base + b_off + ka + ng * 16 * ROWB);
            #pragma unroll
            for (int mt = 0; mt < 2; mt++)
                #pragma unroll
                for (int nt = 0; nt < 8; nt++)
                    MMA(acc[mt][nt], ah[mt], bb[nt]);   // h.M
        }

        // ---- scan (strict >, ascending cols -> first-index argmin) ----
        #pragma unroll
        for (int mt = 0; mt < 2; mt++)
            #pragma unroll
            for (int nt = 0; nt < 8; nt++) {
                const int c0 = q * 128 + wn * 64 + nt * 8 + 2 * (lane & 3);
                #pragma unroll
                for (int rh = 0; rh < 2; rh++) {
                    const int s = mt * 2 + rh;
                    float v0 = acc[mt][nt][rh * 2 + 0];
                    float v1 = acc[mt][nt][rh * 2 + 1];
                    if (v0 > best[s]) { best[s] = v0; bk[s] = c0; }
                    if (v1 > best[s]) { best[s] = v1; bk[s] = c0 + 1; }
                }
            }
    }
    __syncthreads();   // all B reads done -> overlay scratch on OFF_BH

    // ---- per-row reduce: width-4 shfl, then combine the 2 n-warps ----
    #pragma unroll
    for (int s = 0; s < 4; s++) {
        float v = best[s]; int bi = bk[s];
        #pragma unroll
        for (int off = 1; off <= 2; off <<= 1) {
            float ov = __shfl_xor_sync(0xffffffffu, v, off);
            int   oi = __shfl_xor_sync(0xffffffffu, bi, off);
            if (ov > v || (ov == v && oi < bi)) { v = ov; bi = oi; }
        }
        if ((lane & 3) == 0) {
            int row = wm * 32 + (s >> 1) * 16 + (s & 1) * 8 + (lane >> 2);
            ((float*)(smem + OFF_SBV))[row * 2 + wn] = v;
            ((int*)(smem + OFF_SBI))[row * 2 + wn] = bi;
        }
    }
    __syncthreads();
    if (t < 256) {
        float v0 = ((float*)(smem + OFF_SBV))[t * 2 + 0];
        float v1 = ((float*)(smem + OFF_SBV))[t * 2 + 1];
        int   i0 = ((int*)(smem + OFF_SBI))[t * 2 + 0];
        int   i1 = ((int*)(smem + OFF_SBI))[t * 2 + 1];
        int k = (v1 > v0 || (v1 == v0 && i1 < i0)) ? i1 : i0;
        ((int*)(smem + OFF_KIDX))[t] = k;
        if (rowbase + t < n_rows) out_idx[rowbase + t] = (float)k;
    }
    __syncthreads();

    // ---- epilogue: q from g_embT (exact fp32), loss vs x re-read ----
    double lsum = 0.0;
    {
        const int row = t >> 1, hseg = (t & 1) * 32;
        const int grow = rowbase + row;
        if (grow < n_rows) {
            const int k = ((int*)(smem + OFF_KIDX))[row];
            const float4* wp = (const float4*)(g_embT + (size_t)k * DD + hseg);
            const float4* xr = (const float4*)(x + (size_t)grow * DD + hseg);
            float4* qo = (float4*)(out_q + (size_t)grow * DD + hseg);
            #pragma unroll
            for (int j = 0; j < 8; j++) {
                float4 qv = wp[j];
                float4 xv = xr[j];
                qo[j] = qv;
                float e0 = qv.x - xv.x, e1 = qv.y - xv.y;
                float e2 = qv.z - xv.z, e3 = qv.w - xv.w;
                lsum += (double)(e0 * e0 + e1 * e1 + e2 * e2 + e3 * e3);
            }
        }
    }

    // ---- loss reduction -> atomic; last block finalizes + resets ----
    #pragma unroll
    for (int off = 16; off; off >>= 1) lsum += __shfl_down_sync(0xffffffffu, lsum, off);
    double* sred = (double*)(smem + OFF_SRED);
    if (lane == 0) sred[w] = lsum;
    __syncthreads();
    if (t == 0) {
        double v = 0.0;
        #pragma unroll
        for (int i = 0; i < 16; i++) v += sred[i];
        atomicAdd(&g_loss_sum, v);
        __threadfence();
        unsigned prev = atomicAdd(&g_ctr, 1u);
        if (prev == gridDim.x - 1) {
            __threadfence();
            double total = atomicAdd(&g_loss_sum, 0.0);
            *out_loss = (float)(1.25 * total * inv_count);
            g_loss_sum = 0.0;
            g_ctr = 0u;
        }
    }
}

extern "C" void kernel_launch(void* const* d_in, const int* in_sizes, int n_in,
                              void* d_out, int out_size)
{
    const float* x   = (const float*)d_in[0];   // [N, 64]
    const float* emb = (const float*)d_in[1];   // [64, 512]

    const int n_rows = in_sizes[0] / DD;
    float* out      = (float*)d_out;
    float* out_q    = out;
    float* out_idx  = out + (size_t)n_rows * DD;
    float* out_loss = out_idx + n_rows;

    cudaFuncSetAttribute(vq_main_kernel,
                         cudaFuncAttributeMaxDynamicSharedMemorySize, SMEM_TOTAL);

    int grid = (n_rows + BN - 1) / BN;   // 256

    vq_pre_kernel<<<16, 128>>>(emb);
    vq_main_kernel<<<grid, TPB, SMEM_TOTAL>>>(x, out_q, out_idx, out_loss,
                                              n_rows, 1.0 / ((double)n_rows * (double)DD));
}

// round 14
// speedup vs baseline: 1.4774x; 1.2698x over previous
#include <cuda_runtime.h>
#include <cuda_fp16.h>
#include <cstdint>

#define KC   512
#define DD   64
#define TPB  256
#define BN   128
#define LDA  72      // fp16 elems per row (144B)
#define ROWB 144

#define OFF_AH   0                     // 128 x 144B (h of x)
#define OFF_AM   18432                 // 128 x 144B (m of x)
#define OFF_BB   36864                 // 2 bufs x BUFSZ
#define BUFSZ    37376                 // H 18432 + M 18432 + hww 512
#define SMEM_TOTAL (OFF_BB + 2 * BUFSZ + 64)   // 111680 -> 2 CTAs/SM
// post-loop overlay (inside OFF_BB, after final syncthreads)
#define OFF_SBV  (OFF_BB)              // 128x2 f32
#define OFF_SBI  (OFF_BB + 1024)       // 128x2 i32
#define OFF_KIDX (OFF_BB + 2048)       // 128 i32
#define OFF_SRED (OFF_BB + 2560)       // 8 dbl

__device__ __align__(16) __half g_bh[KC * LDA];   // pre-split codebook, h-term [k][d]
__device__ __align__(16) __half g_bm[KC * LDA];   // m-term
__device__ __align__(16) float  g_hww[KC];        // 0.5*||w||^2
__device__ double   g_loss_sum;
__device__ unsigned g_ctr;

#define LDSM4(r0, r1, r2, r3, addr) \
    asm volatile("ldmatrix.sync.aligned.m8n8.x4.shared.b16 {%0,%1,%2,%3}, [%4];" \
                 : "=r"(r0), "=r"(r1), "=r"(r2), "=r"(r3) : "r"(addr))

#define MMA(d, a, b) \
    asm volatile("mma.sync.aligned.m16n8k16.row.col.f32.f16.f16.f32 " \
                 "{%0,%1,%2,%3}, {%4,%5,%6,%7}, {%8,%9}, {%0,%1,%2,%3};" \
                 : "+f"((d)[0]), "+f"((d)[1]), "+f"((d)[2]), "+f"((d)[3]) \
                 : "r"((a)[0]), "r"((a)[1]), "r"((a)[2]), "r"((a)[3]), \
                   "r"((b)[0]), "r"((b)[1]))

#define CPA16(dst, src) \
    asm volatile("cp.async.cg.shared.global [%0], [%1], 16;" :: "r"(dst), "l"(src))

// ---- pre-split: emb [64][512] fp32 -> g_bh/g_bm [512][72] fp16 + g_hww ----
__global__ void __launch_bounds__(128)
vq_pre_kernel(const float* __restrict__ emb)
{
    __shared__ float sp[4][32];
    const int t = threadIdx.x;
    const int c = blockIdx.x * 32 + (t & 31);
    const int dseg = (t >> 5) * 16;

    uint32_t hw[8], mw[8];
    float s = 0.f;
    #pragma unroll
    for (int j = 0; j < 8; j++) {
        float e0 = __ldg(emb + (size_t)(dseg + 2 * j) * KC + c);
        float e1 = __ldg(emb + (size_t)(dseg + 2 * j + 1) * KC + c);
        s = fmaf(e1, e1, fmaf(e0, e0, s));
        __half h0 = __float2half_rn(e0), h1 = __float2half_rn(e1);
        __half m0 = __float2half_rn(e0 - __half2float(h0));
        __half m1 = __float2half_rn(e1 - __half2float(h1));
        hw[j] = (uint32_t)__half_as_ushort(h0) | ((uint32_t)__half_as_ushort(h1) << 16);
        mw[j] = (uint32_t)__half_as_ushort(m0) | ((uint32_t)__half_as_ushort(m1) << 16);
    }
    *(uint4*)(g_bh + c * LDA + dseg)     = make_uint4(hw[0], hw[1], hw[2], hw[3]);
    *(uint4*)(g_bh + c * LDA + dseg + 8) = make_uint4(hw[4], hw[5], hw[6], hw[7]);
    *(uint4*)(g_bm + c * LDA + dseg)     = make_uint4(mw[0], mw[1], mw[2], mw[3]);
    *(uint4*)(g_bm + c * LDA + dseg + 8) = make_uint4(mw[4], mw[5], mw[6], mw[7]);
    sp[t >> 5][t & 31] = s;
    __syncthreads();
    if (t < 32)
        g_hww[blockIdx.x * 32 + t] = 0.5f * (sp[0][t] + sp[1][t] + sp[2][t] + sp[3][t]);
}

// issue one full 128-code quarter (H + M + hww) into buffer buf as one commit group
__device__ __forceinline__ void produce(uint32_t sb, int qtr, int buf, int t)
{
    const char* srcH = (const char*)g_bh + (size_t)qtr * 128 * ROWB;
    const char* srcM = (const char*)g_bm + (size_t)qtr * 128 * ROWB;
    const uint32_t dst = sb + OFF_BB + buf * BUFSZ;
    for (int i = t; i < 1152; i += TPB) {           // 128*144B/16 per term
        CPA16(dst + i * 16, srcH + i * 16);
        CPA16(dst + 18432 + i * 16, srcM + i * 16);
    }
    if (t < 32) CPA16(dst + 36864 + t * 16, (const char*)g_hww + qtr * 512 + t * 16);
    asm volatile("cp.async.commit_group;");
}

__global__ void __launch_bounds__(TPB, 2)
vq_main_kernel(const float* __restrict__ x, float* __restrict__ out_q,
               float* __restrict__ out_idx, float* __restrict__ out_loss,
               int n_rows, double inv_count)
{
    extern __shared__ char smem[];
    const uint32_t sb = (uint32_t)__cvta_generic_to_shared(smem);
    const int t = threadIdx.x, lane = t & 31, w = t >> 5;
    const int wm = w >> 1, wn = w & 1;       // 4 m-warps x 2 n-warps
    const int rowbase = blockIdx.x * BN;

    // prologue: fill both buffers (overlaps the A split below)
    produce(sb, 0, 0, t);
    produce(sb, 1, 1, t);

    // ---- A split: x rows -> h (AH) + m (AM) fp16 tiles ----
    {
        const int row = t >> 1, hseg = (t & 1) * 32;
        const bool valid = (rowbase + row) < n_rows;
        const float4* xr = (const float4*)(x + (size_t)(rowbase + row) * DD + hseg);
        __half* ah = (__half*)(smem + OFF_AH) + row * LDA + hseg;
        __half* am = (__half*)(smem + OFF_AM) + row * LDA + hseg;
        #pragma unroll
        for (int j = 0; j < 8; j++) {
            float4 f = valid ? xr[j] : make_float4(0.f, 0.f, 0.f, 0.f);
            float e[4] = {f.x, f.y, f.z, f.w};
            __half h[4], m[4];
            #pragma unroll
            for (int p = 0; p < 4; p++) {
                h[p] = __float2half_rn(e[p]);
                m[p] = __float2half_rn(e[p] - __half2float(h[p]));
            }
            *(__half2*)(ah + 4 * j)     = __halves2half2(h[0], h[1]);
            *(__half2*)(ah + 4 * j + 2) = __halves2half2(h[2], h[3]);
            *(__half2*)(am + 4 * j)     = __halves2half2(m[0], m[1]);
            *(__half2*)(am + 4 * j + 2) = __halves2half2(m[2], m[3]);
        }
    }
    __syncthreads();   // A tiles visible to all warps

    float best[4];
    int   bk[4];
    #pragma unroll
    for (int s = 0; s < 4; s++) { best[s] = -3.402823466e38f; bk[s] = 0; }

    const uint32_t a_off = (uint32_t)((wm * 32 + (lane & 15)) * ROWB + (((lane >> 4) << 3) << 1));
    const uint32_t b_off = (uint32_t)(((lane & 7) + ((lane >> 4) << 3) + wn * 64) * ROWB
                                      + ((((lane >> 3) & 1) << 3) << 1));

    #pragma unroll 1
    for (int q = 0; q < 4; q++) {
        const int buf = q & 1;
        const uint32_t bbase = sb + OFF_BB + buf * BUFSZ;

        // wait for quarter q's group (q+1's copy keeps running underneath)
        if (q < 3) asm volatile("cp.async.wait_group 1;" ::: "memory");
        else       asm volatile("cp.async.wait_group 0;" ::: "memory");
        __syncthreads();

        // ---- 3-term MMA: acc = hH + mH + hM - 0.5||w||^2 (identical order to champion) ----
        float acc[2][8][4];
        {
            const float* hww = (const float*)(smem + OFF_BB + buf * BUFSZ + 36864);
            #pragma unroll
            for (int nt = 0; nt < 8; nt++) {
                float2 hv = *(const float2*)(hww + wn * 64 + nt * 8 + 2 * (lane & 3));
                #pragma unroll
                for (int mt = 0; mt < 2; mt++) {
                    acc[mt][nt][0] = -hv.x; acc[mt][nt][1] = -hv.y;
                    acc[mt][nt][2] = -hv.x; acc[mt][nt][3] = -hv.y;
                }
            }
        }
        #pragma unroll
        for (int kc = 0; kc < 4; kc++) {
            const uint32_t ka = (uint32_t)(kc * 32);
            uint32_t ah[2][4], am[2][4], bb[8][2];
            LDSM4(ah[0][0], ah[0][1], ah[0][2], ah[0][3], sb + OFF_AH + a_off + ka);
            LDSM4(ah[1][0], ah[1][1], ah[1][2], ah[1][3], sb + OFF_AH + a_off + ka + 16 * ROWB);
            LDSM4(am[0][0], am[0][1], am[0][2], am[0][3], sb + OFF_AM + a_off + ka);
            LDSM4(am[1][0], am[1][1], am[1][2], am[1][3], sb + OFF_AM + a_off + ka + 16 * ROWB);
            #pragma unroll
            for (int ng = 0; ng < 4; ng++)
                LDSM4(bb[2 * ng][0], bb[2 * ng][1], bb[2 * ng + 1][0], bb[2 * ng + 1][1],
                      bbase + b_off + ka + ng * 16 * ROWB);
            #pragma unroll
            for (int mt = 0; mt < 2; mt++)
                #pragma unroll
                for (int nt = 0; nt < 8; nt++) {
                    MMA(acc[mt][nt], ah[mt], bb[nt]);   // h.H
                    MMA(acc[mt][nt], am[mt], bb[nt]);   // m.H
                }
            #pragma unroll
            for (int ng = 0; ng < 4; ng++)
                LDSM4(bb[2 * ng][0], bb[2 * ng][1], bb[2 * ng + 1][0], bb[2 * ng + 1][1],
                      bbase + 18432 + b_off + ka + ng * 16 * ROWB);
            #pragma unroll
            for (int mt = 0; mt < 2; mt++)
                #pragma unroll
                for (int nt = 0; nt < 8; nt++)
                    MMA(acc[mt][nt], ah[mt], bb[nt]);   // h.M
        }
        __syncthreads();   // all warps done reading buf -> safe to refill
        if (q < 2) produce(sb, q + 2, buf, t);   // copy runs under next quarter's MMA

        // ---- scan (strict >, ascending cols -> first-index argmin) ----
        #pragma unroll
        for (int mt = 0; mt < 2; mt++)
            #pragma unroll
            for (int nt = 0; nt < 8; nt++) {
                const int c0 = q * 128 + wn * 64 + nt * 8 + 2 * (lane & 3);
                #pragma unroll
                for (int rh = 0; rh < 2; rh++) {
                    const int s = mt * 2 + rh;
                    float v0 = acc[mt][nt][rh * 2 + 0];
                    float v1 = acc[mt][nt][rh * 2 + 1];
                    if (v0 > best[s]) { best[s] = v0; bk[s] = c0; }
                    if (v1 > best[s]) { best[s] = v1; bk[s] = c0 + 1; }
                }
            }
    }
    __syncthreads();   // all B reads done everywhere -> overlay scratch on OFF_BB

    // ---- per-row reduce: width-4 shfl, then combine the 2 n-warps ----
    #pragma unroll
    for (int s = 0; s < 4; s++) {
        float v = best[s]; int bi = bk[s];
        #pragma unroll
        for (int off = 1; off <= 2; off <<= 1) {
            float ov = __shfl_xor_sync(0xffffffffu, v, off);
            int   oi = __shfl_xor_sync(0xffffffffu, bi, off);
            if (ov > v || (ov == v && oi < bi)) { v = ov; bi = oi; }
        }
        if ((lane & 3) == 0) {
            int row = wm * 32 + (s >> 1) * 16 + (s & 1) * 8 + (lane >> 2);
            ((float*)(smem + OFF_SBV))[row * 2 + wn] = v;
            ((int*)(smem + OFF_SBI))[row * 2 + wn] = bi;
        }
    }
    __syncthreads();
    if (t < 128) {
        float v0 = ((float*)(smem + OFF_SBV))[t * 2 + 0];
        float v1 = ((float*)(smem + OFF_SBV))[t * 2 + 1];
        int   i0 = ((int*)(smem + OFF_SBI))[t * 2 + 0];
        int   i1 = ((int*)(smem + OFF_SBI))[t * 2 + 1];
        int k = (v1 > v0 || (v1 == v0 && i1 < i0)) ? i1 : i0;
        ((int*)(smem + OFF_KIDX))[t] = k;
        if (rowbase + t < n_rows) out_idx[rowbase + t] = (float)k;
    }
    __syncthreads();

    // ---- epilogue (champion's): q = h+m from pre-split (contiguous 144B), loss ----
    double lsum = 0.0;
    {
        const int row = t >> 1, hseg = (t & 1) * 32;
        const int grow = rowbase + row;
        if (grow < n_rows) {
            const int k = ((int*)(smem + OFF_KIDX))[row];
            const __half* gh = g_bh + (size_t)k * LDA + hseg;
            const __half* gm = g_bm + (size_t)k * LDA + hseg;
            const __half* ahp = (const __half*)(smem + OFF_AH) + row * LDA + hseg;
            const __half* amp = (const __half*)(smem + OFF_AM) + row * LDA + hseg;
            float4* qo = (float4*)(out_q + (size_t)grow * DD + hseg);
            #pragma unroll
            for (int j = 0; j < 8; j++) {
                float2 wh0 = __half22float2(*(const __half2*)(gh + 4 * j));
                float2 wh1 = __half22float2(*(const __half2*)(gh + 4 * j + 2));
                float2 wm0 = __half22float2(*(const __half2*)(gm + 4 * j));
                float2 wm1 = __half22float2(*(const __half2*)(gm + 4 * j + 2));
                float q0 = wh0.x + wm0.x, q1 = wh0.y + wm0.y;
                float q2 = wh1.x + wm1.x, q3 = wh1.y + wm1.y;
                qo[j] = make_float4(q0, q1, q2, q3);
                float2 a0 = __half22float2(*(const __half2*)(ahp + 4 * j));
                float2 a1 = __half22float2(*(const __half2*)(ahp + 4 * j + 2));
                float2 b0 = __half22float2(*(const __half2*)(amp + 4 * j));
                float2 b1 = __half22float2(*(const __half2*)(amp + 4 * j + 2));
                float e0 = q0 - (a0.x + b0.x);
                float e1 = q1 - (a0.y + b0.y);
                float e2 = q2 - (a1.x + b1.x);
                float e3 = q3 - (a1.y + b1.y);
                lsum += (double)(e0 * e0 + e1 * e1 + e2 * e2 + e3 * e3);
            }
        }
    }

    // ---- loss reduction -> atomic; last block finalizes + resets ----
    #pragma unroll
    for (int off = 16; off; off >>= 1) lsum += __shfl_down_sync(0xffffffffu, lsum, off);
    double* sred = (double*)(smem + OFF_SRED);
    if (lane == 0) sred[w] = lsum;
    __syncthreads();
    if (t == 0) {
        double v = 0.0;
        #pragma unroll
        for (int i = 0; i < 8; i++) v += sred[i];
        atomicAdd(&g_loss_sum, v);
        __threadfence();
        unsigned prev = atomicAdd(&g_ctr, 1u);
        if (prev == gridDim.x - 1) {
            __threadfence();
            double total = atomicAdd(&g_loss_sum, 0.0);
            *out_loss = (float)(1.25 * total * inv_count);
            g_loss_sum = 0.0;
            g_ctr = 0u;
        }
    }
}

extern "C" void kernel_launch(void* const* d_in, const int* in_sizes, int n_in,
                              void* d_out, int out_size)
{
    const float* x   = (const float*)d_in[0];   // [N, 64]
    const float* emb = (const float*)d_in[1];   // [64, 512]

    const int n_rows = in_sizes[0] / DD;
    float* out      = (float*)d_out;
    float* out_q    = out;
    float* out_idx  = out + (size_t)n_rows * DD;
    float* out_loss = out_idx + n_rows;

    cudaFuncSetAttribute(vq_main_kernel,
                         cudaFuncAttributeMaxDynamicSharedMemorySize, SMEM_TOTAL);

    int grid = (n_rows + BN - 1) / BN;   // 512

    vq_pre_kernel<<<16, 128>>>(emb);
    vq_main_kernel<<<grid, TPB, SMEM_TOTAL>>>(x, out_q, out_idx, out_loss,
                                              n_rows, 1.0 / ((double)n_rows * (double)DD));
}

// round 15
// speedup vs baseline: 1.5384x; 1.0413x over previous
#include <cuda_runtime.h>
#include <cuda_fp16.h>
#include <cstdint>

#define KC   512
#define DD   64
#define TPB  256
#define BN   128
#define LDA  72      // fp16 elems per row (144B)
#define ROWB 144

#define OFF_AH   0                     // 128 x 144B (h of x)
#define OFF_AM   18432                 // 128 x 144B (m of x)
#define OFF_BH   36864                 // 128 x 144B (H of codes quarter)
#define OFF_BM   55296                 // 128 x 144B (M of codes quarter)
#define OFF_HWW  73728                 // 128 f32
#define OFF_SBV  74240                 // 128x2 f32
#define OFF_SBI  75264                 // 128x2 i32
#define OFF_KIDX 76288                 // 128 i32
#define OFF_SRED 76800                 // 8 dbl
#define SMEM_TOTAL 76864               // -> 2 CTAs/SM

#define NPRE 16                        // producer blocks for codebook pre-split

__device__ __align__(16) __half g_bh[KC * LDA];   // pre-split codebook, h-term [k][d]
__device__ __align__(16) __half g_bm[KC * LDA];   // m-term
__device__ __align__(16) float  g_hww[KC];        // 0.5*||w||^2
__device__ double   g_loss_sum;
__device__ unsigned g_ctr;
__device__ unsigned g_pre_ctr;

#define LDSM4(r0, r1, r2, r3, addr) \
    asm volatile("ldmatrix.sync.aligned.m8n8.x4.shared.b16 {%0,%1,%2,%3}, [%4];" \
                 : "=r"(r0), "=r"(r1), "=r"(r2), "=r"(r3) : "r"(addr))

#define MMA(d, a, b) \
    asm volatile("mma.sync.aligned.m16n8k16.row.col.f32.f16.f16.f32 " \
                 "{%0,%1,%2,%3}, {%4,%5,%6,%7}, {%8,%9}, {%0,%1,%2,%3};" \
                 : "+f"((d)[0]), "+f"((d)[1]), "+f"((d)[2]), "+f"((d)[3]) \
                 : "r"((a)[0]), "r"((a)[1]), "r"((a)[2]), "r"((a)[3]), \
                   "r"((b)[0]), "r"((b)[1]))

#define CPA16(dst, src) \
    asm volatile("cp.async.cg.shared.global [%0], [%1], 16;" :: "r"(dst), "l"(src))

__global__ void __launch_bounds__(TPB, 2)
vq_main_kernel(const float* __restrict__ x, const float* __restrict__ emb,
               float* __restrict__ out_q, float* __restrict__ out_idx,
               float* __restrict__ out_loss, int n_rows, double inv_count)
{
    extern __shared__ char smem[];
    const uint32_t sb = (uint32_t)__cvta_generic_to_shared(smem);
    const int t = threadIdx.x, lane = t & 31, w = t >> 5;
    const int wm = w >> 1, wn = w & 1;       // 4 m-warps x 2 n-warps
    const int rowbase = blockIdx.x * BN;

    // ---- producer blocks: pre-split one 32-code slice of the codebook ----
    if (blockIdx.x < NPRE) {
        const int c  = blockIdx.x * 32 + (t & 31);   // code
        const int d0 = (t >> 5) * 8;                 // 8-d segment base
        float e[8];
        uint32_t hw[4], mw[4];
        float s = 0.f;
        #pragma unroll
        for (int j = 0; j < 8; j++) e[j] = __ldg(emb + (size_t)(d0 + j) * KC + c);
        #pragma unroll
        for (int j = 0; j < 4; j++) {
            float e0 = e[2 * j], e1 = e[2 * j + 1];
            s = fmaf(e1, e1, fmaf(e0, e0, s));
            __half h0 = __float2half_rn(e0), h1 = __float2half_rn(e1);
            __half m0 = __float2half_rn(e0 - __half2float(h0));
            __half m1 = __float2half_rn(e1 - __half2float(h1));
            hw[j] = (uint32_t)__half_as_ushort(h0) | ((uint32_t)__half_as_ushort(h1) << 16);
            mw[j] = (uint32_t)__half_as_ushort(m0) | ((uint32_t)__half_as_ushort(m1) << 16);
        }
        *(uint4*)(g_bh + (size_t)c * LDA + d0) = make_uint4(hw[0], hw[1], hw[2], hw[3]);
        *(uint4*)(g_bm + (size_t)c * LDA + d0) = make_uint4(mw[0], mw[1], mw[2], mw[3]);
        float* sp = (float*)(smem + OFF_BH);    // scratch: OFF_BH unused until quarter loop
        sp[(t >> 5) * 32 + (t & 31)] = s;
        __syncthreads();
        if (t < 32) {
            float tot = 0.f;
            #pragma unroll
            for (int j = 0; j < 8; j++) tot += sp[j * 32 + t];
            g_hww[blockIdx.x * 32 + t] = 0.5f * tot;
        }
        __threadfence();
        __syncthreads();
        if (t == 0) atomicAdd(&g_pre_ctr, 1u);
    }

    // ---- A split: x rows -> h (AH) + m (AM) fp16 tiles (independent of codebook) ----
    {
        const int row = t >> 1, hseg = (t & 1) * 32;
        const bool valid = (rowbase + row) < n_rows;
        const float4* xr = (const float4*)(x + (size_t)(rowbase + row) * DD + hseg);
        __half* ah = (__half*)(smem + OFF_AH) + row * LDA + hseg;
        __half* am = (__half*)(smem + OFF_AM) + row * LDA + hseg;
        #pragma unroll
        for (int j = 0; j < 8; j++) {
            float4 f = valid ? xr[j] : make_float4(0.f, 0.f, 0.f, 0.f);
            float e[4] = {f.x, f.y, f.z, f.w};
            __half h[4], m[4];
            #pragma unroll
            for (int p = 0; p < 4; p++) {
                h[p] = __float2half_rn(e[p]);
                m[p] = __float2half_rn(e[p] - __half2float(h[p]));
            }
            *(__half2*)(ah + 4 * j)     = __halves2half2(h[0], h[1]);
            *(__half2*)(ah + 4 * j + 2) = __halves2half2(h[2], h[3]);
            *(__half2*)(am + 4 * j)     = __halves2half2(m[0], m[1]);
            *(__half2*)(am + 4 * j + 2) = __halves2half2(m[2], m[3]);
        }
    }

    // ---- wait for all producers (wave-1 residency guarantees progress) ----
    if (t == 0) {
        while (atomicAdd(&g_pre_ctr, 0u) < NPRE) __nanosleep(64);
        __threadfence();
    }
    __syncthreads();   // also covers A-tile visibility

    float best[4];
    int   bk[4];
    #pragma unroll
    for (int s = 0; s < 4; s++) { best[s] = -3.402823466e38f; bk[s] = 0; }

    const uint32_t a_off = (uint32_t)((wm * 32 + (lane & 15)) * ROWB + (((lane >> 4) << 3) << 1));
    const uint32_t b_off = (uint32_t)(((lane & 7) + ((lane >> 4) << 3) + wn * 64) * ROWB
                                      + ((((lane >> 3) & 1) << 3) << 1));

    #pragma unroll 1
    for (int q = 0; q < 4; q++) {
        const int qbase = q * 128;
        if (q) __syncthreads();   // prior quarter's ldmatrix done; B buffers free

        // ---- bulk-copy pre-split B quarter + hww via cp.async (L2-hot, contiguous) ----
        {
            const char* srcH = (const char*)g_bh + (size_t)qbase * ROWB;
            const char* srcM = (const char*)g_bm + (size_t)qbase * ROWB;
            #pragma unroll
            for (int i = t; i < 1152; i += TPB) {     // 128*144B / 16B
                CPA16(sb + OFF_BH + i * 16, srcH + i * 16);
                CPA16(sb + OFF_BM + i * 16, srcM + i * 16);
            }
            if (t < 32) CPA16(sb + OFF_HWW + t * 16, (const char*)g_hww + qbase * 4 + t * 16);
            asm volatile("cp.async.commit_group;");
            asm volatile("cp.async.wait_group 0;" ::: "memory");
        }
        __syncthreads();

        // ---- MMA: acc = x.w - 0.5||w||^2 via hH + mH + hM, fp32 accum ----
        float acc[2][8][4];
        {
            const float* hww = (const float*)(smem + OFF_HWW);
            #pragma unroll
            for (int nt = 0; nt < 8; nt++) {
                float2 hv = *(const float2*)(hww + wn * 64 + nt * 8 + 2 * (lane & 3));
                #pragma unroll
                for (int mt = 0; mt < 2; mt++) {
                    acc[mt][nt][0] = -hv.x; acc[mt][nt][1] = -hv.y;
                    acc[mt][nt][2] = -hv.x; acc[mt][nt][3] = -hv.y;
                }
            }
        }
        #pragma unroll
        for (int kc = 0; kc < 4; kc++) {
            const uint32_t ka = (uint32_t)(kc * 32);
            uint32_t ah[2][4], am[2][4], bb[8][2];
            LDSM4(ah[0][0], ah[0][1], ah[0][2], ah[0][3], sb + OFF_AH + a_off + ka);
            LDSM4(ah[1][0], ah[1][1], ah[1][2], ah[1][3], sb + OFF_AH + a_off + ka + 16 * ROWB);
            LDSM4(am[0][0], am[0][1], am[0][2], am[0][3], sb + OFF_AM + a_off + ka);
            LDSM4(am[1][0], am[1][1], am[1][2], am[1][3], sb + OFF_AM + a_off + ka + 16 * ROWB);
            #pragma unroll
            for (int ng = 0; ng < 4; ng++)
                LDSM4(bb[2 * ng][0], bb[2 * ng][1], bb[2 * ng + 1][0], bb[2 * ng + 1][1],
                      sb + OFF_BH + b_off + ka + ng * 16 * ROWB);
            #pragma unroll
            for (int mt = 0; mt < 2; mt++)
                #pragma unroll
                for (int nt = 0; nt < 8; nt++) {
                    MMA(acc[mt][nt], ah[mt], bb[nt]);   // h.H
                    MMA(acc[mt][nt], am[mt], bb[nt]);   // m.H
                }
            #pragma unroll
            for (int ng = 0; ng < 4; ng++)
                LDSM4(bb[2 * ng][0], bb[2 * ng][1], bb[2 * ng + 1][0], bb[2 * ng + 1][1],
                      sb + OFF_BM + b_off + ka + ng * 16 * ROWB);
            #pragma unroll
            for (int mt = 0; mt < 2; mt++)
                #pragma unroll
                for (int nt = 0; nt < 8; nt++)
                    MMA(acc[mt][nt], ah[mt], bb[nt]);   // h.M
        }

        // ---- scan: strict >, ascending cols -> first-index argmin semantics ----
        #pragma unroll
        for (int mt = 0; mt < 2; mt++)
            #pragma unroll
            for (int nt = 0; nt < 8; nt++) {
                const int c0 = qbase + wn * 64 + nt * 8 + 2 * (lane & 3);
                #pragma unroll
                for (int rh = 0; rh < 2; rh++) {
                    const int s = mt * 2 + rh;
                    float v0 = acc[mt][nt][rh * 2 + 0];
                    float v1 = acc[mt][nt][rh * 2 + 1];
                    if (v0 > best[s]) { best[s] = v0; bk[s] = c0; }
                    if (v1 > best[s]) { best[s] = v1; bk[s] = c0 + 1; }
                }
            }
    }
    __syncthreads();

    // ---- per-row reduce: width-4 shfl, then combine the 2 n-warps ----
    #pragma unroll
    for (int s = 0; s < 4; s++) {
        float v = best[s]; int bi = bk[s];
        #pragma unroll
        for (int off = 1; off <= 2; off <<= 1) {
            float ov = __shfl_xor_sync(0xffffffffu, v, off);
            int   oi = __shfl_xor_sync(0xffffffffu, bi, off);
            if (ov > v || (ov == v && oi < bi)) { v = ov; bi = oi; }
        }
        if ((lane & 3) == 0) {
            int row = wm * 32 + (s >> 1) * 16 + (s & 1) * 8 + (lane >> 2);
            ((float*)(smem + OFF_SBV))[row * 2 + wn] = v;
            ((int*)(smem + OFF_SBI))[row * 2 + wn] = bi;
        }
    }
    __syncthreads();
    if (t < 128) {
        float v0 = ((float*)(smem + OFF_SBV))[t * 2 + 0];
        float v1 = ((float*)(smem + OFF_SBV))[t * 2 + 1];
        int   i0 = ((int*)(smem + OFF_SBI))[t * 2 + 0];
        int   i1 = ((int*)(smem + OFF_SBI))[t * 2 + 1];
        int k = (v1 > v0 || (v1 == v0 && i1 < i0)) ? i1 : i0;
        ((int*)(smem + OFF_KIDX))[t] = k;
        if (rowbase + t < n_rows) out_idx[rowbase + t] = (float)k;
    }
    __syncthreads();

    // ---- epilogue: q = h+m from pre-split (contiguous 144B gather), loss ----
    double lsum = 0.0;
    {
        const int row = t >> 1, hseg = (t & 1) * 32;
        const int grow = rowbase + row;
        if (grow < n_rows) {
            const int k = ((int*)(smem + OFF_KIDX))[row];
            const __half* gh = g_bh + (size_t)k * LDA + hseg;
            const __half* gm = g_bm + (size_t)k * LDA + hseg;
            const __half* ahp = (const __half*)(smem + OFF_AH) + row * LDA + hseg;
            const __half* amp = (const __half*)(smem + OFF_AM) + row * LDA + hseg;
            float4* qo = (float4*)(out_q + (size_t)grow * DD + hseg);
            #pragma unroll
            for (int j = 0; j < 8; j++) {
                float2 wh0 = __half22float2(*(const __half2*)(gh + 4 * j));
                float2 wh1 = __half22float2(*(const __half2*)(gh + 4 * j + 2));
                float2 wm0 = __half22float2(*(const __half2*)(gm + 4 * j));
                float2 wm1 = __half22float2(*(const __half2*)(gm + 4 * j + 2));
                float q0 = wh0.x + wm0.x, q1 = wh0.y + wm0.y;
                float q2 = wh1.x + wm1.x, q3 = wh1.y + wm1.y;
                qo[j] = make_float4(q0, q1, q2, q3);
                float2 a0 = __half22float2(*(const __half2*)(ahp + 4 * j));
                float2 a1 = __half22float2(*(const __half2*)(ahp + 4 * j + 2));
                float2 b0 = __half22float2(*(const __half2*)(amp + 4 * j));
                float2 b1 = __half22float2(*(const __half2*)(amp + 4 * j + 2));
                float e0 = q0 - (a0.x + b0.x);
                float e1 = q1 - (a0.y + b0.y);
                float e2 = q2 - (a1.x + b1.x);
                float e3 = q3 - (a1.y + b1.y);
                lsum += (double)(e0 * e0 + e1 * e1 + e2 * e2 + e3 * e3);
            }
        }
    }

    // ---- loss reduction -> atomic; last block finalizes + resets all state ----
    #pragma unroll
    for (int off = 16; off; off >>= 1) lsum += __shfl_down_sync(0xffffffffu, lsum, off);
    double* sred = (double*)(smem + OFF_SRED);
    if (lane == 0) sred[w] = lsum;
    __syncthreads();
    if (t == 0) {
        double v = 0.0;
        #pragma unroll
        for (int i = 0; i < 8; i++) v += sred[i];
        atomicAdd(&g_loss_sum, v);
        __threadfence();
        unsigned prev = atomicAdd(&g_ctr, 1u);
        if (prev == gridDim.x - 1) {
            __threadfence();
            double total = atomicAdd(&g_loss_sum, 0.0);
            *out_loss = (float)(1.25 * total * inv_count);
            g_loss_sum = 0.0;
            g_ctr = 0u;
            g_pre_ctr = 0u;   // reset for next graph replay (replays are stream-serialized)
        }
    }
}

extern "C" void kernel_launch(void* const* d_in, const int* in_sizes, int n_in,
                              void* d_out, int out_size)
{
    const float* x   = (const float*)d_in[0];   // [N, 64]
    const float* emb = (const float*)d_in[1];   // [64, 512]

    const int n_rows = in_sizes[0] / DD;
    float* out      = (float*)d_out;
    float* out_q    = out;
    float* out_idx  = out + (size_t)n_rows * DD;
    float* out_loss = out_idx + n_rows;

    cudaFuncSetAttribute(vq_main_kernel,
                         cudaFuncAttributeMaxDynamicSharedMemorySize, SMEM_TOTAL);

    int grid = (n_rows + BN - 1) / BN;   // 512

    vq_main_kernel<<<grid, TPB, SMEM_TOTAL>>>(x, emb, out_q, out_idx, out_loss,
                                              n_rows, 1.0 / ((double)n_rows * (double)DD));
}

// round 16
// speedup vs baseline: 1.7199x; 1.1179x over previous
#include <cuda_runtime.h>
#include <cuda_fp16.h>
#include <cstdint>

#define KC   512
#define DD   64
#define TPB  128
#define BN   64
#define LDA  72      // fp16 elems per row (144B)
#define ROWB 144

#define OFF_AH   0                     // 64 x 144B (h of x)
#define OFF_AM   9216                  // 64 x 144B (m of x)
#define OFF_BH   18432                 // 128 x 144B (H of codes quarter)
#define OFF_BM   36864                 // 128 x 144B (M of codes quarter)
#define OFF_HWW  55296                 // 128 f32
#define OFF_SBV  55808                 // 64x2 f32 (overlay-free tail region)
#define OFF_SBI  56320                 // 64x2 i32
#define OFF_KIDX 56832                 // 64 i32
#define OFF_SRED 57088                 // 4 dbl
#define SMEM_TOTAL 57152               // x4 CTAs = 228608... too big? 228KB=233472 ✓

#define NPRE 16                        // producer blocks for codebook pre-split

__device__ __align__(16) __half g_bh[KC * LDA];   // pre-split codebook, h-term [k][d]
__device__ __align__(16) __half g_bm[KC * LDA];   // m-term
__device__ __align__(16) float  g_hww[KC];        // 0.5*||w||^2
__device__ double   g_loss_sum;
__device__ unsigned g_ctr;
__device__ unsigned g_pre_ctr;

#define LDSM4(r0, r1, r2, r3, addr) \
    asm volatile("ldmatrix.sync.aligned.m8n8.x4.shared.b16 {%0,%1,%2,%3}, [%4];" \
                 : "=r"(r0), "=r"(r1), "=r"(r2), "=r"(r3) : "r"(addr))

#define MMA(d, a, b) \
    asm volatile("mma.sync.aligned.m16n8k16.row.col.f32.f16.f16.f32 " \
                 "{%0,%1,%2,%3}, {%4,%5,%6,%7}, {%8,%9}, {%0,%1,%2,%3};" \
                 : "+f"((d)[0]), "+f"((d)[1]), "+f"((d)[2]), "+f"((d)[3]) \
                 : "r"((a)[0]), "r"((a)[1]), "r"((a)[2]), "r"((a)[3]), \
                   "r"((b)[0]), "r"((b)[1]))

#define CPA16(dst, src) \
    asm volatile("cp.async.cg.shared.global [%0], [%1], 16;" :: "r"(dst), "l"(src))

__global__ void __launch_bounds__(TPB, 4)
vq_main_kernel(const float* __restrict__ x, const float* __restrict__ emb,
               float* __restrict__ out_q, float* __restrict__ out_idx,
               float* __restrict__ out_loss, int n_rows, double inv_count)
{
    extern __shared__ char smem[];
    const uint32_t sb = (uint32_t)__cvta_generic_to_shared(smem);
    const int t = threadIdx.x, lane = t & 31, w = t >> 5;
    const int wm = w >> 1, wn = w & 1;       // 2 m-warps x 2 n-warps
    const int rowbase = blockIdx.x * BN;

    // ---- producer blocks: pre-split one 32-code slice of the codebook ----
    if (blockIdx.x < NPRE) {
        const int c  = blockIdx.x * 32 + (t & 31);   // code
        const int d0 = (t >> 5) * 16;                // 16-d segment base
        float s = 0.f;
        uint32_t hw[8], mw[8];
        #pragma unroll
        for (int j = 0; j < 8; j++) {
            float e0 = __ldg(emb + (size_t)(d0 + 2 * j) * KC + c);
            float e1 = __ldg(emb + (size_t)(d0 + 2 * j + 1) * KC + c);
            s = fmaf(e1, e1, fmaf(e0, e0, s));
            __half h0 = __float2half_rn(e0), h1 = __float2half_rn(e1);
            __half m0 = __float2half_rn(e0 - __half2float(h0));
            __half m1 = __float2half_rn(e1 - __half2float(h1));
            hw[j] = (uint32_t)__half_as_ushort(h0) | ((uint32_t)__half_as_ushort(h1) << 16);
            mw[j] = (uint32_t)__half_as_ushort(m0) | ((uint32_t)__half_as_ushort(m1) << 16);
        }
        *(uint4*)(g_bh + (size_t)c * LDA + d0)     = make_uint4(hw[0], hw[1], hw[2], hw[3]);
        *(uint4*)(g_bh + (size_t)c * LDA + d0 + 8) = make_uint4(hw[4], hw[5], hw[6], hw[7]);
        *(uint4*)(g_bm + (size_t)c * LDA + d0)     = make_uint4(mw[0], mw[1], mw[2], mw[3]);
        *(uint4*)(g_bm + (size_t)c * LDA + d0 + 8) = make_uint4(mw[4], mw[5], mw[6], mw[7]);
        float* sp = (float*)(smem + OFF_BH);    // scratch: OFF_BH unused until quarter loop
        sp[(t >> 5) * 32 + (t & 31)] = s;
        __syncthreads();
        if (t < 32)
            g_hww[blockIdx.x * 32 + t] = 0.5f * (sp[t] + sp[32 + t] + sp[64 + t] + sp[96 + t]);
        __threadfence();
        __syncthreads();
        if (t == 0) atomicAdd(&g_pre_ctr, 1u);
    }

    // ---- A split: 64 x rows -> h (AH) + m (AM) fp16 tiles ----
    {
        const int row = t >> 1, hseg = (t & 1) * 32;
        const bool valid = (rowbase + row) < n_rows;
        const float4* xr = (const float4*)(x + (size_t)(rowbase + row) * DD + hseg);
        __half* ah = (__half*)(smem + OFF_AH) + row * LDA + hseg;
        __half* am = (__half*)(smem + OFF_AM) + row * LDA + hseg;
        #pragma unroll
        for (int j = 0; j < 8; j++) {
            float4 f = valid ? xr[j] : make_float4(0.f, 0.f, 0.f, 0.f);
            float e[4] = {f.x, f.y, f.z, f.w};
            __half h[4], m[4];
            #pragma unroll
            for (int p = 0; p < 4; p++) {
                h[p] = __float2half_rn(e[p]);
                m[p] = __float2half_rn(e[p] - __half2float(h[p]));
            }
            *(__half2*)(ah + 4 * j)     = __halves2half2(h[0], h[1]);
            *(__half2*)(ah + 4 * j + 2) = __halves2half2(h[2], h[3]);
            *(__half2*)(am + 4 * j)     = __halves2half2(m[0], m[1]);
            *(__half2*)(am + 4 * j + 2) = __halves2half2(m[2], m[3]);
        }
    }

    // ---- wait for all producers (wave-1 residency guarantees progress) ----
    if (t == 0) {
        while (atomicAdd(&g_pre_ctr, 0u) < NPRE) __nanosleep(64);
        __threadfence();
    }
    __syncthreads();   // also covers A-tile visibility

    float best[4];
    int   bk[4];
    #pragma unroll
    for (int s = 0; s < 4; s++) { best[s] = -3.402823466e38f; bk[s] = 0; }

    const uint32_t a_off = (uint32_t)((wm * 32 + (lane & 15)) * ROWB + (((lane >> 4) << 3) << 1));
    const uint32_t b_off = (uint32_t)(((lane & 7) + ((lane >> 4) << 3) + wn * 64) * ROWB
                                      + ((((lane >> 3) & 1) << 3) << 1));

    #pragma unroll 1
    for (int q = 0; q < 4; q++) {
        const int qbase = q * 128;
        if (q) __syncthreads();   // prior quarter's ldmatrix done; B buffers free

        // ---- bulk-copy pre-split B quarter + hww via cp.async (L2-hot) ----
        {
            const char* srcH = (const char*)g_bh + (size_t)qbase * ROWB;
            const char* srcM = (const char*)g_bm + (size_t)qbase * ROWB;
            #pragma unroll
            for (int i = t; i < 1152; i += TPB) {     // 128*144B / 16B
                CPA16(sb + OFF_BH + i * 16, srcH + i * 16);
                CPA16(sb + OFF_BM + i * 16, srcM + i * 16);
            }
            if (t < 32) CPA16(sb + OFF_HWW + t * 16, (const char*)g_hww + qbase * 4 + t * 16);
            asm volatile("cp.async.commit_group;");
            asm volatile("cp.async.wait_group 0;" ::: "memory");
        }
        __syncthreads();

        // ---- MMA: acc = x.w - 0.5||w||^2 via hH + mH + hM, fp32 accum ----
        float acc[2][8][4];
        {
            const float* hww = (const float*)(smem + OFF_HWW);
            #pragma unroll
            for (int nt = 0; nt < 8; nt++) {
                float2 hv = *(const float2*)(hww + wn * 64 + nt * 8 + 2 * (lane & 3));
                #pragma unroll
                for (int mt = 0; mt < 2; mt++) {
                    acc[mt][nt][0] = -hv.x; acc[mt][nt][1] = -hv.y;
                    acc[mt][nt][2] = -hv.x; acc[mt][nt][3] = -hv.y;
                }
            }
        }
        #pragma unroll
        for (int kc = 0; kc < 4; kc++) {
            const uint32_t ka = (uint32_t)(kc * 32);
            uint32_t ah[2][4], am[2][4], bb[8][2];
            LDSM4(ah[0][0], ah[0][1], ah[0][2], ah[0][3], sb + OFF_AH + a_off + ka);
            LDSM4(ah[1][0], ah[1][1], ah[1][2], ah[1][3], sb + OFF_AH + a_off + ka + 16 * ROWB);
            LDSM4(am[0][0], am[0][1], am[0][2], am[0][3], sb + OFF_AM + a_off + ka);
            LDSM4(am[1][0], am[1][1], am[1][2], am[1][3], sb + OFF_AM + a_off + ka + 16 * ROWB);
            #pragma unroll
            for (int ng = 0; ng < 4; ng++)
                LDSM4(bb[2 * ng][0], bb[2 * ng][1], bb[2 * ng + 1][0], bb[2 * ng + 1][1],
                      sb + OFF_BH + b_off + ka + ng * 16 * ROWB);
            #pragma unroll
            for (int mt = 0; mt < 2; mt++)
                #pragma unroll
                for (int nt = 0; nt < 8; nt++) {
                    MMA(acc[mt][nt], ah[mt], bb[nt]);   // h.H
                    MMA(acc[mt][nt], am[mt], bb[nt]);   // m.H
                }
            #pragma unroll
            for (int ng = 0; ng < 4; ng++)
                LDSM4(bb[2 * ng][0], bb[2 * ng][1], bb[2 * ng + 1][0], bb[2 * ng + 1][1],
                      sb + OFF_BM + b_off + ka + ng * 16 * ROWB);
            #pragma unroll
            for (int mt = 0; mt < 2; mt++)
                #pragma unroll
                for (int nt = 0; nt < 8; nt++)
                    MMA(acc[mt][nt], ah[mt], bb[nt]);   // h.M
        }

        // ---- scan: strict >, ascending cols -> first-index argmin semantics ----
        #pragma unroll
        for (int mt = 0; mt < 2; mt++)
            #pragma unroll
            for (int nt = 0; nt < 8; nt++) {
                const int c0 = qbase + wn * 64 + nt * 8 + 2 * (lane & 3);
                #pragma unroll
                for (int rh = 0; rh < 2; rh++) {
                    const int s = mt * 2 + rh;
                    float v0 = acc[mt][nt][rh * 2 + 0];
                    float v1 = acc[mt][nt][rh * 2 + 1];
                    if (v0 > best[s]) { best[s] = v0; bk[s] = c0; }
                    if (v1 > best[s]) { best[s] = v1; bk[s] = c0 + 1; }
                }
            }
    }
    __syncthreads();

    // ---- per-row reduce: width-4 shfl, then combine the 2 n-warps ----
    #pragma unroll
    for (int s = 0; s < 4; s++) {
        float v = best[s]; int bi = bk[s];
        #pragma unroll
        for (int off = 1; off <= 2; off <<= 1) {
            float ov = __shfl_xor_sync(0xffffffffu, v, off);
            int   oi = __shfl_xor_sync(0xffffffffu, bi, off);
            if (ov > v || (ov == v && oi < bi)) { v = ov; bi = oi; }
        }
        if ((lane & 3) == 0) {
            int row = wm * 32 + (s >> 1) * 16 + (s & 1) * 8 + (lane >> 2);
            ((float*)(smem + OFF_SBV))[row * 2 + wn] = v;
            ((int*)(smem + OFF_SBI))[row * 2 + wn] = bi;
        }
    }
    __syncthreads();
    if (t < BN) {
        float v0 = ((float*)(smem + OFF_SBV))[t * 2 + 0];
        float v1 = ((float*)(smem + OFF_SBV))[t * 2 + 1];
        int   i0 = ((int*)(smem + OFF_SBI))[t * 2 + 0];
        int   i1 = ((int*)(smem + OFF_SBI))[t * 2 + 1];
        int k = (v1 > v0 || (v1 == v0 && i1 < i0)) ? i1 : i0;
        ((int*)(smem + OFF_KIDX))[t] = k;
        if (rowbase + t < n_rows) out_idx[rowbase + t] = (float)k;
    }
    __syncthreads();

    // ---- epilogue: q = h+m from pre-split (contiguous 144B gather), loss ----
    double lsum = 0.0;
    {
        const int row = t >> 1, hseg = (t & 1) * 32;
        const int grow = rowbase + row;
        if (grow < n_rows) {
            const int k = ((int*)(smem + OFF_KIDX))[row];
            const __half* gh = g_bh + (size_t)k * LDA + hseg;
            const __half* gm = g_bm + (size_t)k * LDA + hseg;
            const __half* ahp = (const __half*)(smem + OFF_AH) + row * LDA + hseg;
            const __half* amp = (const __half*)(smem + OFF_AM) + row * LDA + hseg;
            float4* qo = (float4*)(out_q + (size_t)grow * DD + hseg);
            #pragma unroll
            for (int j = 0; j < 8; j++) {
                float2 wh0 = __half22float2(*(const __half2*)(gh + 4 * j));
                float2 wh1 = __half22float2(*(const __half2*)(gh + 4 * j + 2));
                float2 wm0 = __half22float2(*(const __half2*)(gm + 4 * j));
                float2 wm1 = __half22float2(*(const __half2*)(gm + 4 * j + 2));
                float q0 = wh0.x + wm0.x, q1 = wh0.y + wm0.y;
                float q2 = wh1.x + wm1.x, q3 = wh1.y + wm1.y;
                qo[j] = make_float4(q0, q1, q2, q3);
                float2 a0 = __half22float2(*(const __half2*)(ahp + 4 * j));
                float2 a1 = __half22float2(*(const __half2*)(ahp + 4 * j + 2));
                float2 b0 = __half22float2(*(const __half2*)(amp + 4 * j));
                float2 b1 = __half22float2(*(const __half2*)(amp + 4 * j + 2));
                float e0 = q0 - (a0.x + b0.x);
                float e1 = q1 - (a0.y + b0.y);
                float e2 = q2 - (a1.x + b1.x);
                float e3 = q3 - (a1.y + b1.y);
                lsum += (double)(e0 * e0 + e1 * e1 + e2 * e2 + e3 * e3);
            }
        }
    }

    // ---- loss reduction -> atomic; last block finalizes + resets all state ----
    #pragma unroll
    for (int off = 16; off; off >>= 1) lsum += __shfl_down_sync(0xffffffffu, lsum, off);
    double* sred = (double*)(smem + OFF_SRED);
    if (lane == 0) sred[w] = lsum;
    __syncthreads();
    if (t == 0) {
        double v = sred[0] + sred[1] + sred[2] + sred[3];
        atomicAdd(&g_loss_sum, v);
        __threadfence();
        unsigned prev = atomicAdd(&g_ctr, 1u);
        if (prev == gridDim.x - 1) {
            __threadfence();
            double total = atomicAdd(&g_loss_sum, 0.0);
            *out_loss = (float)(1.25 * total * inv_count);
            g_loss_sum = 0.0;
            g_ctr = 0u;
            g_pre_ctr = 0u;   // reset for next graph replay (replays stream-serialized)
        }
    }
}

extern "C" void kernel_launch(void* const* d_in, const int* in_sizes, int n_in,
                              void* d_out, int out_size)
{
    const float* x   = (const float*)d_in[0];   // [N, 64]
    const float* emb = (const float*)d_in[1];   // [64, 512]

    const int n_rows = in_sizes[0] / DD;
    float* out      = (float*)d_out;
    float* out_q    = out;
    float* out_idx  = out + (size_t)n_rows * DD;
    float* out_loss = out_idx + n_rows;

    cudaFuncSetAttribute(vq_main_kernel,
                         cudaFuncAttributeMaxDynamicSharedMemorySize, SMEM_TOTAL);

    int grid = (n_rows + BN - 1) / BN;   // 1024

    vq_main_kernel<<<grid, TPB, SMEM_TOTAL>>>(x, emb, out_q, out_idx, out_loss,
                                              n_rows, 1.0 / ((double)n_rows * (double)DD));
}